// round 5
// baseline (speedup 1.0000x reference)
#include <cuda_runtime.h>
#include <cuda_bf16.h>
#include <stdint.h>

#define B 32
#define H 512
#define W 512
#define HW (H*W)            // 262144
#define WW 16               // words per row (512/32)

__device__ unsigned char g_gray[B*HW];       // 8.4 MB
__device__ unsigned      g_weak[B*H*WW];     // 1 MB
__device__ unsigned      g_strong[B*H*WW];   // 1 MB

// ---------------- Kernel 1: RGB -> gray (u8)  [proven 18.9us] ----------------
__device__ __forceinline__ float u8f(float v) {
    float t = __fmul_rn(__fadd_rn(v, 1.0f), 128.0f);
    t = fminf(fmaxf(t, 0.0f), 255.0f);
    return floorf(t);
}

__device__ __forceinline__ unsigned char grayf(float r, float g, float b) {
    float t = __fadd_rn(__fadd_rn(__fmul_rn(0.299f, u8f(r)),
                                  __fmul_rn(0.587f, u8f(g))),
                        __fmul_rn(0.114f, u8f(b)));
    return (unsigned char)rintf(t);   // round half to even, matches jnp.round
}

__global__ void k_gray(const float* __restrict__ x) {
    int i = blockIdx.x * blockDim.x + threadIdx.x;   // pixel4 index
    if (i >= B * (HW/4)) return;
    int b  = i >> 16;
    int p4 = i & 65535;
    const float4* base = (const float4*)(x + (size_t)b * 3 * HW);
    float4 r  = base[p4];
    float4 g  = base[65536 + p4];
    float4 bl = base[131072 + p4];
    uchar4 o;
    o.x = grayf(r.x, g.x, bl.x);
    o.y = grayf(r.y, g.y, bl.y);
    o.z = grayf(r.z, g.z, bl.z);
    o.w = grayf(r.w, g.w, bl.w);
    ((uchar4*)g_gray)[i] = o;
}

// ------------- Kernel 2: Sobel + NMS + thresholds -> bitmasks (unchanged) -------------
__global__ void k_sobel(void) {
    __shared__ int G[12][132];   // gray tile with halo 2
    __shared__ int M[10][132];   // mag tile with halo 1

    int b = blockIdx.z;
    int tileX = blockIdx.x * 128, tileY = blockIdx.y * 8;
    int tx = threadIdx.x, ty = threadIdx.y;
    int tid = ty * 128 + tx;
    const unsigned char* gb = g_gray + (size_t)b * HW;

    for (int i = tid; i < 12 * 132; i += 1024) {
        int r = i / 132, c = i - r * 132;
        int gy = min(max(tileY - 2 + r, 0), H - 1);   // replicate border
        int gx = min(max(tileX - 2 + c, 0), W - 1);
        G[r][c] = gb[gy * W + gx];
    }
    __syncthreads();

    for (int i = tid; i < 10 * 130; i += 1024) {
        int r = i / 130, c = i - r * 130;
        int py = tileY - 1 + r, px = tileX - 1 + c;
        int m = 0;
        if (py >= 0 && py < H && px >= 0 && px < W) {   // mag zero-padded outside
            int r0 = r + 1, c0 = c + 1;
            int gxv = (G[r0-1][c0+1] + 2*G[r0][c0+1] + G[r0+1][c0+1])
                    - (G[r0-1][c0-1] + 2*G[r0][c0-1] + G[r0+1][c0-1]);
            int gyv = (G[r0+1][c0-1] + 2*G[r0+1][c0] + G[r0+1][c0+1])
                    - (G[r0-1][c0-1] + 2*G[r0-1][c0] + G[r0-1][c0+1]);
            m = abs(gxv) + abs(gyv);
        }
        M[r][c] = m;
    }
    __syncthreads();

    int py = tileY + ty, px = tileX + tx;
    int r0 = ty + 2, c0 = tx + 2;
    int gxv = (G[r0-1][c0+1] + 2*G[r0][c0+1] + G[r0+1][c0+1])
            - (G[r0-1][c0-1] + 2*G[r0][c0-1] + G[r0+1][c0-1]);
    int gyv = (G[r0+1][c0-1] + 2*G[r0+1][c0] + G[r0+1][c0+1])
            - (G[r0-1][c0-1] + 2*G[r0-1][c0] + G[r0-1][c0+1]);
    int mr = ty + 1, mc = tx + 1;
    int m  = M[mr][mc];

    int ax = abs(gxv), ay = abs(gyv);
    double dax = (double)ax, day = (double)ay;
    int q1, q2;
    if (day < 0.41421356237309503 * dax) {
        q1 = M[mr][mc + 1]; q2 = M[mr][mc - 1];
    } else if (day > 2.414213562373095 * dax) {
        q1 = M[mr + 1][mc]; q2 = M[mr - 1][mc];
    } else if ((gxv > 0) == (gyv > 0)) {
        q1 = M[mr + 1][mc + 1]; q2 = M[mr - 1][mc - 1];
    } else {
        q1 = M[mr - 1][mc + 1]; q2 = M[mr + 1][mc - 1];
    }
    bool keep   = (m >= q1) && (m >= q2);
    bool weak   = keep && (m > 40);
    bool strong = keep && (m > 85);

    unsigned wmask = __ballot_sync(0xffffffffu, weak);
    unsigned smask = __ballot_sync(0xffffffffu, strong);
    if ((tx & 31) == 0) {
        int wi = b * (H * WW) + py * WW + (px >> 5);
        g_weak[wi]   = wmask;
        g_strong[wi] = smask;
    }
}

// ------------- Kernel 3: hysteresis with shrinking active window -------------
// 4 strips/image, 100-row halo. 6 rows/thread in registers, shfl horizontal halos,
// SMEM vertical boundaries (double-buffered), one __syncthreads_or per iteration.
// NEW: warp-granular shrinking window — at iteration t only warps whose rows are
// within chessboard distance (100 - t) of the strip core need to compute; this is
// exact (needed-set shrinks 1 row/side/iter; stale rows provably never re-read).
#define RPT 6
#define NSLOT (64*RPT)      // 384

__global__ void __launch_bounds__(1024, 1) k_hyst(float* __restrict__ out) {
    __shared__ unsigned Bt[2][64][16];   // h[0] of each ygroup
    __shared__ unsigned Bb[2][64][16];   // h[RPT-1] of each ygroup
    __shared__ unsigned SS[NSLOT * 16];  // final state for coalesced output (24KB)

    int blk = blockIdx.x;
    int b = blk >> 2, s = blk & 3;
    int ybase = max(0, 128 * s - 100);
    int yend  = min(512, 128 * s + 228);
    int nrows = yend - ybase;
    int coreBase = 128 * s - ybase;      // slot index of first core row

    int tid = threadIdx.x;
    int xw = tid & 15;
    int yg = tid >> 4;
    int slot0 = yg * RPT;

    // warp activity horizon: warp covers slots [wslot0, wslot0+12)
    int wslot0 = (tid >> 5) * (2 * RPT);
    int mind = max(0, max(coreBase - (wslot0 + 2 * RPT - 1),
                          wslot0 - (coreBase + 127)));
    int tmax = 100 - mind;               // compute while t <= tmax

    const unsigned* wb = g_weak   + b * (H * WW);
    const unsigned* sb = g_strong + b * (H * WW);

    unsigned wk[RPT], st[RPT];
#pragma unroll
    for (int i = 0; i < RPT; i++) {
        int slot = slot0 + i;
        if (slot < nrows) {
            int gy = ybase + slot;
            wk[i] = wb[gy * WW + xw];
            st[i] = sb[gy * WW + xw];
        } else { wk[i] = 0u; st[i] = 0u; }
    }
    unsigned lmask = (xw == 0)  ? 0u : 0xffffffffu;
    unsigned rmask = (xw == 15) ? 0u : 0xffffffffu;

    unsigned d = 1u;   // force first iteration
    for (int t = 0; t < 100; ++t) {
        int tb = t & 1;
        bool act = (t <= tmax);
        unsigned h[RPT];
        if (act) {
#pragma unroll
            for (int i = 0; i < RPT; i++) {
                unsigned c = st[i];
                unsigned l = __shfl_up_sync(0xffffffffu, c, 1) & lmask;
                unsigned r = __shfl_down_sync(0xffffffffu, c, 1) & rmask;
                h[i] = c | __funnelshift_l(l, c, 1) | __funnelshift_r(c, r, 1);
            }
            Bt[tb][yg][xw] = h[0];
            Bb[tb][yg][xw] = h[RPT - 1];
        }

        // barrier + OR-reduce over "did previous update change anything"
        int conv = __syncthreads_or((int)d);
        if (!conv) break;   // previous update was a fixed point -> rest are identity

        if (act) {
            unsigned hup = (yg > 0)  ? Bb[tb][yg - 1][xw] : 0u;
            unsigned hdn = (yg < 63) ? Bt[tb][yg + 1][xw] : 0u;

            d = 0u;
            unsigned ns;
            ns = wk[0] & (hup | h[0] | h[1]);             d |= ns ^ st[0]; st[0] = ns;
#pragma unroll
            for (int i = 1; i < RPT - 1; i++) {
                ns = wk[i] & (h[i-1] | h[i] | h[i+1]);    d |= ns ^ st[i]; st[i] = ns;
            }
            ns = wk[RPT-1] & (h[RPT-2] | h[RPT-1] | hdn); d |= ns ^ st[RPT-1]; st[RPT-1] = ns;
        } else {
            d = 0u;
        }
    }
    __syncthreads();

    // dump state to SMEM, then expand core rows to float output (coalesced)
#pragma unroll
    for (int i = 0; i < RPT; i++) SS[(slot0 + i) * 16 + xw] = st[i];
    __syncthreads();

    float* ob = out + (size_t)b * HW + (size_t)(128 * s) * W;
    for (int p4 = tid; p4 < 128 * 128; p4 += 1024) {
        int y = p4 >> 7;            // core row 0..127
        int x4 = p4 & 127;          // group of 4 px
        unsigned w = SS[(coreBase + y) * 16 + (x4 >> 3)];
        int sh = (x4 & 7) * 4;
        float4 o;
        o.x = ((w >> (sh + 0)) & 1u) ? 255.0f : 0.0f;
        o.y = ((w >> (sh + 1)) & 1u) ? 255.0f : 0.0f;
        o.z = ((w >> (sh + 2)) & 1u) ? 255.0f : 0.0f;
        o.w = ((w >> (sh + 3)) & 1u) ? 255.0f : 0.0f;
        ((float4*)(ob + y * W))[x4] = o;
    }
}

extern "C" void kernel_launch(void* const* d_in, const int* in_sizes, int n_in,
                              void* d_out, int out_size) {
    const float* x = (const float*)d_in[0];
    float* out = (float*)d_out;

    k_gray<<<(B * (HW/4) + 255) / 256, 256>>>(x);
    k_sobel<<<dim3(W/128, H/8, B), dim3(128, 8)>>>();
    k_hyst<<<B * 4, 1024>>>(out);
}

// round 7
// speedup vs baseline: 1.3496x; 1.3496x over previous
#include <cuda_runtime.h>
#include <cuda_bf16.h>
#include <stdint.h>

#define B 32
#define H 512
#define W 512
#define HW (H*W)            // 262144
#define WW 16               // words per row (512/32)

__device__ unsigned char g_gray[B*HW];       // 8.4 MB
__device__ unsigned      g_weak[B*H*WW];     // 1 MB
__device__ unsigned      g_strong[B*H*WW];   // 1 MB

// ---------------- Kernel 1: RGB -> gray (u8)  [proven 18.9us] ----------------
__device__ __forceinline__ float u8f(float v) {
    float t = __fmul_rn(__fadd_rn(v, 1.0f), 128.0f);
    t = fminf(fmaxf(t, 0.0f), 255.0f);
    return floorf(t);
}

__device__ __forceinline__ unsigned char grayf(float r, float g, float b) {
    float t = __fadd_rn(__fadd_rn(__fmul_rn(0.299f, u8f(r)),
                                  __fmul_rn(0.587f, u8f(g))),
                        __fmul_rn(0.114f, u8f(b)));
    return (unsigned char)rintf(t);   // round half to even, matches jnp.round
}

__global__ void k_gray(const float* __restrict__ x) {
    int i = blockIdx.x * blockDim.x + threadIdx.x;   // pixel4 index
    if (i >= B * (HW/4)) return;
    int b  = i >> 16;
    int p4 = i & 65535;
    const float4* base = (const float4*)(x + (size_t)b * 3 * HW);
    float4 r  = base[p4];
    float4 g  = base[65536 + p4];
    float4 bl = base[131072 + p4];
    uchar4 o;
    o.x = grayf(r.x, g.x, bl.x);
    o.y = grayf(r.y, g.y, bl.y);
    o.z = grayf(r.z, g.z, bl.z);
    o.w = grayf(r.w, g.w, bl.w);
    ((uchar4*)g_gray)[i] = o;
}

// ------------- Kernel 2: Sobel + NMS + thresholds (int64 bin predicate, no FP64) -------------
// CORRECTED constants: tan(22.5deg)*2^40 = 455432628200 (+-3e2), tan(67.5deg)*2^40 =
// 2654455883752. Decision-identical to exact-tan double compare (which passed):
// nearest rational ay/ax with ax,ay<=1020 is 3.7e-7 away => tolerance +-4e5.
#define T1LO 455432628200ULL
#define T2HI 2654455883752ULL

__global__ void k_sobel(void) {
    __shared__ int G[12][132];   // gray tile with halo 2
    __shared__ int M[10][132];   // mag tile with halo 1

    int b = blockIdx.z;
    int tileX = blockIdx.x * 128, tileY = blockIdx.y * 8;
    int tx = threadIdx.x, ty = threadIdx.y;
    int tid = ty * 128 + tx;
    const unsigned char* gb = g_gray + (size_t)b * HW;

    for (int i = tid; i < 12 * 132; i += 1024) {
        int r = i / 132, c = i - r * 132;
        int gy = min(max(tileY - 2 + r, 0), H - 1);   // replicate border
        int gx = min(max(tileX - 2 + c, 0), W - 1);
        G[r][c] = gb[gy * W + gx];
    }
    __syncthreads();

    for (int i = tid; i < 10 * 130; i += 1024) {
        int r = i / 130, c = i - r * 130;
        int py = tileY - 1 + r, px = tileX - 1 + c;
        int m = 0;
        if (py >= 0 && py < H && px >= 0 && px < W) {   // mag zero-padded outside
            int r0 = r + 1, c0 = c + 1;
            int gxv = (G[r0-1][c0+1] + 2*G[r0][c0+1] + G[r0+1][c0+1])
                    - (G[r0-1][c0-1] + 2*G[r0][c0-1] + G[r0+1][c0-1]);
            int gyv = (G[r0+1][c0-1] + 2*G[r0+1][c0] + G[r0+1][c0+1])
                    - (G[r0-1][c0-1] + 2*G[r0-1][c0] + G[r0-1][c0+1]);
            m = abs(gxv) + abs(gyv);
        }
        M[r][c] = m;
    }
    __syncthreads();

    int py = tileY + ty, px = tileX + tx;
    int r0 = ty + 2, c0 = tx + 2;
    int gxv = (G[r0-1][c0+1] + 2*G[r0][c0+1] + G[r0+1][c0+1])
            - (G[r0-1][c0-1] + 2*G[r0][c0-1] + G[r0+1][c0-1]);
    int gyv = (G[r0+1][c0-1] + 2*G[r0+1][c0] + G[r0+1][c0+1])
            - (G[r0-1][c0-1] + 2*G[r0-1][c0] + G[r0-1][c0+1]);
    int mr = ty + 1, mc = tx + 1;
    int m  = M[mr][mc];

    unsigned long long ax = (unsigned long long)abs(gxv);
    unsigned long long ay40 = ((unsigned long long)abs(gyv)) << 40;
    int q1, q2;
    if (ay40 < T1LO * ax) {                    // b0: ~horizontal gradient
        q1 = M[mr][mc + 1]; q2 = M[mr][mc - 1];
    } else if (ay40 > T2HI * ax) {             // b2: ~vertical
        q1 = M[mr + 1][mc]; q2 = M[mr - 1][mc];
    } else if ((gxv > 0) == (gyv > 0)) {       // b1
        q1 = M[mr + 1][mc + 1]; q2 = M[mr - 1][mc - 1];
    } else {                                   // b3
        q1 = M[mr - 1][mc + 1]; q2 = M[mr + 1][mc - 1];
    }
    bool keep   = (m >= q1) && (m >= q2);
    bool weak   = keep && (m > 40);
    bool strong = keep && (m > 85);

    unsigned wmask = __ballot_sync(0xffffffffu, weak);
    unsigned smask = __ballot_sync(0xffffffffu, strong);
    if ((tx & 31) == 0) {
        int wi = b * (H * WW) + py * WW + (px >> 5);
        g_weak[wi]   = wmask;
        g_strong[wi] = smask;
    }
}

// ------------- Kernel 3: hysteresis, 64-bit column pairs -------------
// 4 strips/image, 100-row halo (exact for 100 iters). Thread owns a uint64
// (2 adjacent words) x 3 rows. Horizontal halo = 1 boundary bit per side:
// 2x 32-bit shfl per row. Vertical group boundaries via SMEM (double-buffered),
// one __syncthreads_or per iteration. Warp-granular shrinking active window.
#define RPT64 3
#define NSLOT (128*RPT64)    // 384

__global__ void __launch_bounds__(1024, 1) k_hyst(float* __restrict__ out) {
    __shared__ union {
        struct {
            unsigned long long Bt[2][128][8];  // h[0] per ygroup      (16KB)
            unsigned long long Bb[2][128][8];  // h[RPT64-1] per group (16KB)
        } x;
        unsigned SS[NSLOT * 16];               // final state (24KB)
    } sm;

    int blk = blockIdx.x;
    int b = blk >> 2, s = blk & 3;
    int ybase = max(0, 128 * s - 100);
    int yend  = min(512, 128 * s + 228);
    int nrows = yend - ybase;
    int coreBase = 128 * s - ybase;      // slot index of first core row

    int tid = threadIdx.x;
    int xp = tid & 7;                    // column pair (64 px) index
    int yg = tid >> 3;                   // 0..127
    int slot0 = yg * RPT64;

    // warp activity horizon: warp covers slots [wslot0, wslot0+12)
    int wslot0 = (tid >> 5) * 12;
    int mind = max(0, max(coreBase - (wslot0 + 11), wslot0 - (coreBase + 127)));
    int tmax = 100 - mind;

    const unsigned long long* wb = (const unsigned long long*)(g_weak   + b * (H * WW));
    const unsigned long long* sb = (const unsigned long long*)(g_strong + b * (H * WW));

    unsigned long long wk[RPT64], st[RPT64];
#pragma unroll
    for (int i = 0; i < RPT64; i++) {
        int slot = slot0 + i;
        if (slot < nrows) {
            int gy = ybase + slot;
            wk[i] = wb[gy * 8 + xp];
            st[i] = sb[gy * 8 + xp];
        } else { wk[i] = 0ull; st[i] = 0ull; }
    }
    unsigned lmask = (xp == 0) ? 0u : 0xffffffffu;
    unsigned rmask = (xp == 7) ? 0u : 0xffffffffu;

    unsigned d = 1u;   // force first iteration
    for (int t = 0; t < 100; ++t) {
        int tb = t & 1;
        bool act = (t <= tmax);
        unsigned long long h[RPT64];
        if (act) {
#pragma unroll
            for (int i = 0; i < RPT64; i++) {
                unsigned long long c = st[i];
                unsigned hi = (unsigned)(c >> 32), lo = (unsigned)c;
                unsigned lh = __shfl_up_sync(0xffffffffu, hi, 1) & lmask;   // left msb
                unsigned rl = __shfl_down_sync(0xffffffffu, lo, 1) & rmask; // right lsb
                h[i] = c | (c << 1) | (c >> 1)
                     | (unsigned long long)(lh >> 31)
                     | ((unsigned long long)(rl & 1u) << 63);
            }
            sm.x.Bt[tb][yg][xp] = h[0];
            sm.x.Bb[tb][yg][xp] = h[RPT64 - 1];
        }

        int conv = __syncthreads_or((int)d);
        if (!conv) break;   // previous update was a fixed point -> rest identity

        if (act) {
            unsigned long long hup = (yg > 0)   ? sm.x.Bb[tb][yg - 1][xp] : 0ull;
            unsigned long long hdn = (yg < 127) ? sm.x.Bt[tb][yg + 1][xp] : 0ull;

            unsigned long long d64 = 0ull, ns;
            ns = wk[0] & (hup | h[0] | h[1]);  d64 |= ns ^ st[0]; st[0] = ns;
            ns = wk[1] & (h[0] | h[1] | h[2]); d64 |= ns ^ st[1]; st[1] = ns;
            ns = wk[2] & (h[1] | h[2] | hdn);  d64 |= ns ^ st[2]; st[2] = ns;
            d = (d64 != 0ull) ? 1u : 0u;
        } else {
            d = 0u;
        }
    }
    __syncthreads();

    // dump state to SMEM (32-bit words), then expand core rows to float output
#pragma unroll
    for (int i = 0; i < RPT64; i++) {
        sm.SS[(slot0 + i) * 16 + 2 * xp]     = (unsigned)st[i];
        sm.SS[(slot0 + i) * 16 + 2 * xp + 1] = (unsigned)(st[i] >> 32);
    }
    __syncthreads();

    float* ob = out + (size_t)b * HW + (size_t)(128 * s) * W;
    for (int p4 = tid; p4 < 128 * 128; p4 += 1024) {
        int y = p4 >> 7;            // core row 0..127
        int x4 = p4 & 127;          // group of 4 px
        unsigned w = sm.SS[(coreBase + y) * 16 + (x4 >> 3)];
        int sh = (x4 & 7) * 4;
        float4 o;
        o.x = ((w >> (sh + 0)) & 1u) ? 255.0f : 0.0f;
        o.y = ((w >> (sh + 1)) & 1u) ? 255.0f : 0.0f;
        o.z = ((w >> (sh + 2)) & 1u) ? 255.0f : 0.0f;
        o.w = ((w >> (sh + 3)) & 1u) ? 255.0f : 0.0f;
        ((float4*)(ob + y * W))[x4] = o;
    }
}

extern "C" void kernel_launch(void* const* d_in, const int* in_sizes, int n_in,
                              void* d_out, int out_size) {
    const float* x = (const float*)d_in[0];
    float* out = (float*)d_out;

    k_gray<<<(B * (HW/4) + 255) / 256, 256>>>(x);
    k_sobel<<<dim3(W/128, H/8, B), dim3(128, 8)>>>();
    k_hyst<<<B * 4, 1024>>>(out);
}

// round 8
// speedup vs baseline: 1.8800x; 1.3930x over previous
#include <cuda_runtime.h>
#include <cuda_bf16.h>
#include <stdint.h>

#define B 32
#define H 512
#define W 512
#define HW (H*W)            // 262144
#define WW 16               // words per row (512/32)

__device__ unsigned g_weak[B*H*WW];     // 1 MB
__device__ unsigned g_strong[B*H*WW];   // 1 MB

// ---- exact gray math (matches reference bit-for-bit) ----
__device__ __forceinline__ float u8f(float v) {
    float t = __fmul_rn(__fadd_rn(v, 1.0f), 128.0f);
    t = fminf(fmaxf(t, 0.0f), 255.0f);
    return floorf(t);
}

__device__ __forceinline__ int grayf(float r, float g, float b) {
    float t = __fadd_rn(__fadd_rn(__fmul_rn(0.299f, u8f(r)),
                                  __fmul_rn(0.587f, u8f(g))),
                        __fmul_rn(0.114f, u8f(b)));
    return (int)rintf(t);   // round half to even, matches jnp.round
}

// int64 angle-bin constants: tan(22.5)*2^40, tan(67.5)*2^40 (decision-exact, see R6)
#define T1LO 455432628200ULL
#define T2HI 2654455883752ULL

// ------------- Fused Kernel 1: RGB -> gray -> Sobel -> NMS -> bitmasks -------------
// Tile 128x32 core, block (128,8), 4 core rows per thread.
// Gray computed from RGB directly into SMEM with halo 2 (36x132), read amp 1.16x.
__global__ void __launch_bounds__(1024) k_gsobel(const float* __restrict__ x) {
    __shared__ int G[36][132];   // gray tile with halo 2 (19.0 KB)
    __shared__ int M[34][132];   // mag tile with halo 1  (17.9 KB)

    int b = blockIdx.z;
    int tileX = blockIdx.x * 128, tileY = blockIdx.y * 32;
    int tx = threadIdx.x, ty = threadIdx.y;
    int tid = ty * 128 + tx;
    const float* xr = x + (size_t)b * 3 * HW;

    // gray for 36x132 halo tile, straight from RGB (replicate border)
    for (int i = tid; i < 36 * 132; i += 1024) {
        int r = i / 132, c = i - r * 132;
        int gy = min(max(tileY - 2 + r, 0), H - 1);
        int gx = min(max(tileX - 2 + c, 0), W - 1);
        int p = gy * W + gx;
        G[r][c] = grayf(xr[p], xr[HW + p], xr[2 * HW + p]);
    }
    __syncthreads();

    // |gx|+|gy| magnitude for 34x130 (halo 1), zero outside image
    for (int i = tid; i < 34 * 130; i += 1024) {
        int r = i / 130, c = i - r * 130;
        int py = tileY - 1 + r, px = tileX - 1 + c;
        int m = 0;
        if (py >= 0 && py < H && px >= 0 && px < W) {
            int r0 = r + 1, c0 = c + 1;
            int gxv = (G[r0-1][c0+1] + 2*G[r0][c0+1] + G[r0+1][c0+1])
                    - (G[r0-1][c0-1] + 2*G[r0][c0-1] + G[r0+1][c0-1]);
            int gyv = (G[r0+1][c0-1] + 2*G[r0+1][c0] + G[r0+1][c0+1])
                    - (G[r0-1][c0-1] + 2*G[r0-1][c0] + G[r0-1][c0+1]);
            m = abs(gxv) + abs(gyv);
        }
        M[r][c] = m;
    }
    __syncthreads();

    // NMS + double threshold for 4 core rows per thread; ballot along x
#pragma unroll
    for (int k = 0; k < 4; k++) {
        int ly = ty * 4 + k;               // core row in tile 0..31
        int py = tileY + ly, px = tileX + tx;
        int r0 = ly + 2, c0 = tx + 2;      // G index of this pixel
        int gxv = (G[r0-1][c0+1] + 2*G[r0][c0+1] + G[r0+1][c0+1])
                - (G[r0-1][c0-1] + 2*G[r0][c0-1] + G[r0+1][c0-1]);
        int gyv = (G[r0+1][c0-1] + 2*G[r0+1][c0] + G[r0+1][c0+1])
                - (G[r0-1][c0-1] + 2*G[r0-1][c0] + G[r0-1][c0+1]);
        int mr = ly + 1, mc = tx + 1;      // M index
        int m  = M[mr][mc];

        unsigned long long ax = (unsigned long long)abs(gxv);
        unsigned long long ay40 = ((unsigned long long)abs(gyv)) << 40;
        int q1, q2;
        if (ay40 < T1LO * ax) {                    // b0: ~horizontal gradient
            q1 = M[mr][mc + 1]; q2 = M[mr][mc - 1];
        } else if (ay40 > T2HI * ax) {             // b2: ~vertical
            q1 = M[mr + 1][mc]; q2 = M[mr - 1][mc];
        } else if ((gxv > 0) == (gyv > 0)) {       // b1
            q1 = M[mr + 1][mc + 1]; q2 = M[mr - 1][mc - 1];
        } else {                                   // b3
            q1 = M[mr - 1][mc + 1]; q2 = M[mr + 1][mc - 1];
        }
        bool keep   = (m >= q1) && (m >= q2);
        bool weak   = keep && (m > 40);
        bool strong = keep && (m > 85);

        unsigned wmask = __ballot_sync(0xffffffffu, weak);
        unsigned smask = __ballot_sync(0xffffffffu, strong);
        if ((tx & 31) == 0) {
            int wi = b * (H * WW) + py * WW + (px >> 5);
            g_weak[wi]   = wmask;
            g_strong[wi] = smask;
        }
    }
}

// ------------- Kernel 2: hysteresis, 64-bit column pairs (unchanged from R6) -------------
#define RPT64 3
#define NSLOT (128*RPT64)    // 384

__global__ void __launch_bounds__(1024, 1) k_hyst(float* __restrict__ out) {
    __shared__ union {
        struct {
            unsigned long long Bt[2][128][8];  // h[0] per ygroup      (16KB)
            unsigned long long Bb[2][128][8];  // h[RPT64-1] per group (16KB)
        } x;
        unsigned SS[NSLOT * 16];               // final state (24KB)
    } sm;

    int blk = blockIdx.x;
    int b = blk >> 2, s = blk & 3;
    int ybase = max(0, 128 * s - 100);
    int yend  = min(512, 128 * s + 228);
    int nrows = yend - ybase;
    int coreBase = 128 * s - ybase;      // slot index of first core row

    int tid = threadIdx.x;
    int xp = tid & 7;                    // column pair (64 px) index
    int yg = tid >> 3;                   // 0..127
    int slot0 = yg * RPT64;

    // warp activity horizon: warp covers slots [wslot0, wslot0+12)
    int wslot0 = (tid >> 5) * 12;
    int mind = max(0, max(coreBase - (wslot0 + 11), wslot0 - (coreBase + 127)));
    int tmax = 100 - mind;

    const unsigned long long* wb = (const unsigned long long*)(g_weak   + b * (H * WW));
    const unsigned long long* sb = (const unsigned long long*)(g_strong + b * (H * WW));

    unsigned long long wk[RPT64], st[RPT64];
#pragma unroll
    for (int i = 0; i < RPT64; i++) {
        int slot = slot0 + i;
        if (slot < nrows) {
            int gy = ybase + slot;
            wk[i] = wb[gy * 8 + xp];
            st[i] = sb[gy * 8 + xp];
        } else { wk[i] = 0ull; st[i] = 0ull; }
    }
    unsigned lmask = (xp == 0) ? 0u : 0xffffffffu;
    unsigned rmask = (xp == 7) ? 0u : 0xffffffffu;

    unsigned d = 1u;   // force first iteration
    for (int t = 0; t < 100; ++t) {
        int tb = t & 1;
        bool act = (t <= tmax);
        unsigned long long h[RPT64];
        if (act) {
#pragma unroll
            for (int i = 0; i < RPT64; i++) {
                unsigned long long c = st[i];
                unsigned hi = (unsigned)(c >> 32), lo = (unsigned)c;
                unsigned lh = __shfl_up_sync(0xffffffffu, hi, 1) & lmask;   // left msb
                unsigned rl = __shfl_down_sync(0xffffffffu, lo, 1) & rmask; // right lsb
                h[i] = c | (c << 1) | (c >> 1)
                     | (unsigned long long)(lh >> 31)
                     | ((unsigned long long)(rl & 1u) << 63);
            }
            sm.x.Bt[tb][yg][xp] = h[0];
            sm.x.Bb[tb][yg][xp] = h[RPT64 - 1];
        }

        int conv = __syncthreads_or((int)d);
        if (!conv) break;   // previous update was a fixed point -> rest identity

        if (act) {
            unsigned long long hup = (yg > 0)   ? sm.x.Bb[tb][yg - 1][xp] : 0ull;
            unsigned long long hdn = (yg < 127) ? sm.x.Bt[tb][yg + 1][xp] : 0ull;

            unsigned long long d64 = 0ull, ns;
            ns = wk[0] & (hup | h[0] | h[1]);  d64 |= ns ^ st[0]; st[0] = ns;
            ns = wk[1] & (h[0] | h[1] | h[2]); d64 |= ns ^ st[1]; st[1] = ns;
            ns = wk[2] & (h[1] | h[2] | hdn);  d64 |= ns ^ st[2]; st[2] = ns;
            d = (d64 != 0ull) ? 1u : 0u;
        } else {
            d = 0u;
        }
    }
    __syncthreads();

    // dump state to SMEM (32-bit words), then expand core rows to float output
#pragma unroll
    for (int i = 0; i < RPT64; i++) {
        sm.SS[(slot0 + i) * 16 + 2 * xp]     = (unsigned)st[i];
        sm.SS[(slot0 + i) * 16 + 2 * xp + 1] = (unsigned)(st[i] >> 32);
    }
    __syncthreads();

    float* ob = out + (size_t)b * HW + (size_t)(128 * s) * W;
    for (int p4 = tid; p4 < 128 * 128; p4 += 1024) {
        int y = p4 >> 7;            // core row 0..127
        int x4 = p4 & 127;          // group of 4 px
        unsigned w = sm.SS[(coreBase + y) * 16 + (x4 >> 3)];
        int sh = (x4 & 7) * 4;
        float4 o;
        o.x = ((w >> (sh + 0)) & 1u) ? 255.0f : 0.0f;
        o.y = ((w >> (sh + 1)) & 1u) ? 255.0f : 0.0f;
        o.z = ((w >> (sh + 2)) & 1u) ? 255.0f : 0.0f;
        o.w = ((w >> (sh + 3)) & 1u) ? 255.0f : 0.0f;
        ((float4*)(ob + y * W))[x4] = o;
    }
}

extern "C" void kernel_launch(void* const* d_in, const int* in_sizes, int n_in,
                              void* d_out, int out_size) {
    const float* x = (const float*)d_in[0];
    float* out = (float*)d_out;

    k_gsobel<<<dim3(W/128, H/32, B), dim3(128, 8)>>>(x);
    k_hyst<<<B * 4, 1024>>>(out);
}

// round 9
// speedup vs baseline: 2.3632x; 1.2570x over previous
#include <cuda_runtime.h>
#include <cuda_bf16.h>
#include <stdint.h>

#define B 32
#define H 512
#define W 512
#define HW (H*W)            // 262144
#define WW 16               // words per row (512/32)

__device__ unsigned g_weak[B*H*WW];     // 1 MB
__device__ unsigned g_strong[B*H*WW];   // 1 MB

// ---- exact gray math (matches reference bit-for-bit) ----
__device__ __forceinline__ float u8f(float v) {
    float t = __fmul_rn(__fadd_rn(v, 1.0f), 128.0f);
    t = fminf(fmaxf(t, 0.0f), 255.0f);
    return floorf(t);
}

__device__ __forceinline__ int grayf(float r, float g, float b) {
    float t = __fadd_rn(__fadd_rn(__fmul_rn(0.299f, u8f(r)),
                                  __fmul_rn(0.587f, u8f(g))),
                        __fmul_rn(0.114f, u8f(b)));
    return (int)rintf(t);   // round half to even, matches jnp.round
}

// int64 angle-bin constants: tan(22.5)*2^40, tan(67.5)*2^40 (decision-exact, see R6)
#define T1LO 455432628200ULL
#define T2HI 2654455883752ULL

// ------------- Fused Kernel 1: RGB -> gray -> Sobel -> NMS -> bitmasks -------------
// Tile 128x32 core, block (128,8). Gray tile G spans cols tileX-4..tileX+131 (136)
// so the fill is aligned float4 loads + int4 stores. Sobel computed ONCE per core
// pixel (registers, separable 6-row window); NMS reuses registers, reads only
// neighbor magnitudes from SMEM.
__global__ void __launch_bounds__(1024) k_gsobel(const float* __restrict__ x) {
    __shared__ int G[36][136];   // gray, rows tileY-2..+33, cols tileX-4..+131 (19.1 KB)
    __shared__ int M[34][132];   // mag,  rows tileY-1..+32, cols tileX-1..+130 (17.9 KB)

    int b = blockIdx.z;
    int tileX = blockIdx.x * 128, tileY = blockIdx.y * 32;
    int tx = threadIdx.x, ty = threadIdx.y;
    int tid = ty * 128 + tx;
    const float* xr = x + (size_t)b * 3 * HW;

    // ---- gray fill: 36 rows x 34 aligned 4-pixel groups ----
    for (int i = tid; i < 36 * 34; i += 1024) {
        int r = i / 34, j = i - r * 34;
        int gy = min(max(tileY - 2 + r, 0), H - 1);
        int gx0 = tileX - 4 + 4 * j;
        int4 o;
        if (gx0 >= 0 && gx0 <= W - 4) {          // aligned fast path (all interior tiles)
            const float4* pr = (const float4*)(xr + (size_t)gy * W) + (gx0 >> 2);
            float4 rr = pr[0];
            float4 gg = pr[HW / 4];
            float4 bb = pr[2 * (HW / 4)];
            o.x = grayf(rr.x, gg.x, bb.x);
            o.y = grayf(rr.y, gg.y, bb.y);
            o.z = grayf(rr.z, gg.z, bb.z);
            o.w = grayf(rr.w, gg.w, bb.w);
        } else {                                  // border clamp (x-edge tiles only)
            int v[4];
#pragma unroll
            for (int e = 0; e < 4; e++) {
                int gx = min(max(gx0 + e, 0), W - 1);
                int p = gy * W + gx;
                v[e] = grayf(xr[p], xr[HW + p], xr[2 * HW + p]);
            }
            o.x = v[0]; o.y = v[1]; o.z = v[2]; o.w = v[3];
        }
        *(int4*)&G[r][4 * j] = o;
    }
    __syncthreads();

    // ---- Sobel for own 4 core pixels (rows ty*4+k), separable, kept in registers ----
    int gxr[4], gyr[4], mreg[4];
    {
        int cl = tx + 3, cc = tx + 4, cr = tx + 5;   // G cols: px-1, px, px+1
        int rb = ty * 4 + 1;                         // G row of (core row ly=ty*4) - 1
        int L[6], C[6], R[6];
#pragma unroll
        for (int q = 0; q < 6; q++) {
            L[q] = G[rb + q][cl];
            C[q] = G[rb + q][cc];
            R[q] = G[rb + q][cr];
        }
#pragma unroll
        for (int k = 0; k < 4; k++) {
            int vr  = R[k] + 2 * R[k + 1] + R[k + 2];
            int vl  = L[k] + 2 * L[k + 1] + L[k + 2];
            int hs0 = L[k] + 2 * C[k] + R[k];
            int hs2 = L[k + 2] + 2 * C[k + 2] + R[k + 2];
            gxr[k] = vr - vl;
            gyr[k] = hs2 - hs0;
            mreg[k] = abs(gxr[k]) + abs(gyr[k]);
            M[ty * 4 + k + 1][tx + 1] = mreg[k];
        }
    }

    // ---- halo mag ring: 324 pixels (rows -1,32 full width; cols -1,128 for rows 0..31) ----
    if (tid < 324) {
        int ly, lx;
        if (tid < 130)      { ly = -1;        lx = tid - 1; }
        else if (tid < 260) { ly = 32;        lx = tid - 131; }
        else if (tid < 292) { ly = tid - 260; lx = -1; }
        else                { ly = tid - 292; lx = 128; }
        int py = tileY + ly, px = tileX + lx;
        int m = 0;
        if (py >= 0 && py < H && px >= 0 && px < W) {   // mag zero-padded outside image
            int r0 = ly + 2, c0 = lx + 4;
            int gxv = (G[r0-1][c0+1] + 2*G[r0][c0+1] + G[r0+1][c0+1])
                    - (G[r0-1][c0-1] + 2*G[r0][c0-1] + G[r0+1][c0-1]);
            int gyv = (G[r0+1][c0-1] + 2*G[r0+1][c0] + G[r0+1][c0+1])
                    - (G[r0-1][c0-1] + 2*G[r0-1][c0] + G[r0-1][c0+1]);
            m = abs(gxv) + abs(gyv);
        }
        M[ly + 1][lx + 1] = m;
    }
    __syncthreads();

    // ---- NMS + thresholds from registers; only q1/q2 come from SMEM ----
#pragma unroll
    for (int k = 0; k < 4; k++) {
        int ly = ty * 4 + k;
        int py = tileY + ly, px = tileX + tx;
        int gxv = gxr[k], gyv = gyr[k], m = mreg[k];
        int mr = ly + 1, mc = tx + 1;

        unsigned long long ax = (unsigned long long)abs(gxv);
        unsigned long long ay40 = ((unsigned long long)abs(gyv)) << 40;
        int q1, q2;
        if (ay40 < T1LO * ax) {                    // b0: ~horizontal gradient
            q1 = M[mr][mc + 1]; q2 = M[mr][mc - 1];
        } else if (ay40 > T2HI * ax) {             // b2: ~vertical
            q1 = M[mr + 1][mc]; q2 = M[mr - 1][mc];
        } else if ((gxv > 0) == (gyv > 0)) {       // b1
            q1 = M[mr + 1][mc + 1]; q2 = M[mr - 1][mc - 1];
        } else {                                   // b3
            q1 = M[mr - 1][mc + 1]; q2 = M[mr + 1][mc - 1];
        }
        bool keep   = (m >= q1) && (m >= q2);
        bool weak   = keep && (m > 40);
        bool strong = keep && (m > 85);

        unsigned wmask = __ballot_sync(0xffffffffu, weak);
        unsigned smask = __ballot_sync(0xffffffffu, strong);
        if ((tx & 31) == 0) {
            int wi = b * (H * WW) + py * WW + (px >> 5);
            g_weak[wi]   = wmask;
            g_strong[wi] = smask;
        }
    }
}

// ------------- Kernel 2: hysteresis, 64-bit column pairs (unchanged, 10.5us) -------------
#define RPT64 3
#define NSLOT (128*RPT64)    // 384

__global__ void __launch_bounds__(1024, 1) k_hyst(float* __restrict__ out) {
    __shared__ union {
        struct {
            unsigned long long Bt[2][128][8];  // h[0] per ygroup      (16KB)
            unsigned long long Bb[2][128][8];  // h[RPT64-1] per group (16KB)
        } x;
        unsigned SS[NSLOT * 16];               // final state (24KB)
    } sm;

    int blk = blockIdx.x;
    int b = blk >> 2, s = blk & 3;
    int ybase = max(0, 128 * s - 100);
    int yend  = min(512, 128 * s + 228);
    int nrows = yend - ybase;
    int coreBase = 128 * s - ybase;      // slot index of first core row

    int tid = threadIdx.x;
    int xp = tid & 7;                    // column pair (64 px) index
    int yg = tid >> 3;                   // 0..127
    int slot0 = yg * RPT64;

    int wslot0 = (tid >> 5) * 12;
    int mind = max(0, max(coreBase - (wslot0 + 11), wslot0 - (coreBase + 127)));
    int tmax = 100 - mind;

    const unsigned long long* wb = (const unsigned long long*)(g_weak   + b * (H * WW));
    const unsigned long long* sb = (const unsigned long long*)(g_strong + b * (H * WW));

    unsigned long long wk[RPT64], st[RPT64];
#pragma unroll
    for (int i = 0; i < RPT64; i++) {
        int slot = slot0 + i;
        if (slot < nrows) {
            int gy = ybase + slot;
            wk[i] = wb[gy * 8 + xp];
            st[i] = sb[gy * 8 + xp];
        } else { wk[i] = 0ull; st[i] = 0ull; }
    }
    unsigned lmask = (xp == 0) ? 0u : 0xffffffffu;
    unsigned rmask = (xp == 7) ? 0u : 0xffffffffu;

    unsigned d = 1u;   // force first iteration
    for (int t = 0; t < 100; ++t) {
        int tb = t & 1;
        bool act = (t <= tmax);
        unsigned long long h[RPT64];
        if (act) {
#pragma unroll
            for (int i = 0; i < RPT64; i++) {
                unsigned long long c = st[i];
                unsigned hi = (unsigned)(c >> 32), lo = (unsigned)c;
                unsigned lh = __shfl_up_sync(0xffffffffu, hi, 1) & lmask;   // left msb
                unsigned rl = __shfl_down_sync(0xffffffffu, lo, 1) & rmask; // right lsb
                h[i] = c | (c << 1) | (c >> 1)
                     | (unsigned long long)(lh >> 31)
                     | ((unsigned long long)(rl & 1u) << 63);
            }
            sm.x.Bt[tb][yg][xp] = h[0];
            sm.x.Bb[tb][yg][xp] = h[RPT64 - 1];
        }

        int conv = __syncthreads_or((int)d);
        if (!conv) break;   // previous update was a fixed point -> rest identity

        if (act) {
            unsigned long long hup = (yg > 0)   ? sm.x.Bb[tb][yg - 1][xp] : 0ull;
            unsigned long long hdn = (yg < 127) ? sm.x.Bt[tb][yg + 1][xp] : 0ull;

            unsigned long long d64 = 0ull, ns;
            ns = wk[0] & (hup | h[0] | h[1]);  d64 |= ns ^ st[0]; st[0] = ns;
            ns = wk[1] & (h[0] | h[1] | h[2]); d64 |= ns ^ st[1]; st[1] = ns;
            ns = wk[2] & (h[1] | h[2] | hdn);  d64 |= ns ^ st[2]; st[2] = ns;
            d = (d64 != 0ull) ? 1u : 0u;
        } else {
            d = 0u;
        }
    }
    __syncthreads();

#pragma unroll
    for (int i = 0; i < RPT64; i++) {
        sm.SS[(slot0 + i) * 16 + 2 * xp]     = (unsigned)st[i];
        sm.SS[(slot0 + i) * 16 + 2 * xp + 1] = (unsigned)(st[i] >> 32);
    }
    __syncthreads();

    float* ob = out + (size_t)b * HW + (size_t)(128 * s) * W;
    for (int p4 = tid; p4 < 128 * 128; p4 += 1024) {
        int y = p4 >> 7;            // core row 0..127
        int x4 = p4 & 127;          // group of 4 px
        unsigned w = sm.SS[(coreBase + y) * 16 + (x4 >> 3)];
        int sh = (x4 & 7) * 4;
        float4 o;
        o.x = ((w >> (sh + 0)) & 1u) ? 255.0f : 0.0f;
        o.y = ((w >> (sh + 1)) & 1u) ? 255.0f : 0.0f;
        o.z = ((w >> (sh + 2)) & 1u) ? 255.0f : 0.0f;
        o.w = ((w >> (sh + 3)) & 1u) ? 255.0f : 0.0f;
        ((float4*)(ob + y * W))[x4] = o;
    }
}

extern "C" void kernel_launch(void* const* d_in, const int* in_sizes, int n_in,
                              void* d_out, int out_size) {
    const float* x = (const float*)d_in[0];
    float* out = (float*)d_out;

    k_gsobel<<<dim3(W/128, H/32, B), dim3(128, 8)>>>(x);
    k_hyst<<<B * 4, 1024>>>(out);
}

// round 10
// speedup vs baseline: 2.3892x; 1.0110x over previous
#include <cuda_runtime.h>
#include <cuda_bf16.h>
#include <stdint.h>

#define B 32
#define H 512
#define W 512
#define HW (H*W)            // 262144
#define WW 16               // words per row (512/32)

__device__ unsigned g_weak[B*H*WW];     // 1 MB
__device__ unsigned g_strong[B*H*WW];   // 1 MB

// ---- exact gray math ----
// u8f: floor(clip((v+1)*0.5*256,0,255)). Single FFMA is bit-identical to
// fadd+fmul: *128 is exact scaling and RN is scaling-equivariant here.
__device__ __forceinline__ float u8f(float v) {
    float t = __fmaf_rn(v, 128.0f, 128.0f);
    t = fminf(fmaxf(t, 0.0f), 255.0f);
    return floorf(t);
}

__device__ __forceinline__ int grayf(float r, float g, float b) {
    float t = __fadd_rn(__fadd_rn(__fmul_rn(0.299f, u8f(r)),
                                  __fmul_rn(0.587f, u8f(g))),
                        __fmul_rn(0.114f, u8f(b)));
    return (int)rintf(t);   // round half to even, matches jnp.round
}

// angle-bin constants at 2^30 scale (fit u32 -> IMAD.WIDE.U32):
// tan(22.5)*2^30 = 444758425 (+-2), tan(67.5)*2^30 = 2592242073 (+-2).
// Nearest realizable rational ay/ax is 3.7e-7 (resp 2.2e-6) from the boundary
// => tolerance +-400 (resp +-2300): decision-exact.
#define T1_30 444758425ULL
#define T2_30 2592242073ULL

// ------------- Fused Kernel 1: RGB -> gray -> Sobel -> NMS -> bitmasks -------------
__global__ void __launch_bounds__(1024) k_gsobel(const float* __restrict__ x) {
    __shared__ int G[36][136];   // gray, rows tileY-2..+33, cols tileX-4..+131
    __shared__ int M[34][132];   // mag,  rows tileY-1..+32, cols tileX-1..+130

    int b = blockIdx.z;
    int tileX = blockIdx.x * 128, tileY = blockIdx.y * 32;
    int tx = threadIdx.x, ty = threadIdx.y;
    int tid = ty * 128 + tx;
    const float* xr = x + (size_t)b * 3 * HW;

    // ---- gray fill: 36 rows x 34 aligned 4-pixel groups ----
    for (int i = tid; i < 36 * 34; i += 1024) {
        int r = i / 34, j = i - r * 34;
        int gy = min(max(tileY - 2 + r, 0), H - 1);
        int gx0 = tileX - 4 + 4 * j;
        int4 o;
        if (gx0 >= 0 && gx0 <= W - 4) {          // aligned fast path
            const float4* pr = (const float4*)(xr + (size_t)gy * W) + (gx0 >> 2);
            float4 rr = pr[0];
            float4 gg = pr[HW / 4];
            float4 bb = pr[2 * (HW / 4)];
            o.x = grayf(rr.x, gg.x, bb.x);
            o.y = grayf(rr.y, gg.y, bb.y);
            o.z = grayf(rr.z, gg.z, bb.z);
            o.w = grayf(rr.w, gg.w, bb.w);
        } else {                                  // border clamp (x-edge tiles only)
            int v[4];
#pragma unroll
            for (int e = 0; e < 4; e++) {
                int gx = min(max(gx0 + e, 0), W - 1);
                int p = gy * W + gx;
                v[e] = grayf(xr[p], xr[HW + p], xr[2 * HW + p]);
            }
            o.x = v[0]; o.y = v[1]; o.z = v[2]; o.w = v[3];
        }
        *(int4*)&G[r][4 * j] = o;
    }
    __syncthreads();

    // ---- Sobel for own 4 core pixels, separable, shared row-sums ----
    int gxr[4], gyr[4], mreg[4];
    {
        int cl = tx + 3, cc = tx + 4, cr = tx + 5;   // G cols: px-1, px, px+1
        int rb = ty * 4 + 1;                         // G row of (core row ly) - 1
        int L[6], C[6], R[6], hs[6];
#pragma unroll
        for (int q = 0; q < 6; q++) {
            L[q] = G[rb + q][cl];
            C[q] = G[rb + q][cc];
            R[q] = G[rb + q][cr];
            hs[q] = (L[q] + R[q]) + 2 * C[q];        // shared: hs2_k == hs0_{k+2}
        }
#pragma unroll
        for (int k = 0; k < 4; k++) {
            int vr = R[k] + 2 * R[k + 1] + R[k + 2];
            int vl = L[k] + 2 * L[k + 1] + L[k + 2];
            gxr[k] = vr - vl;
            gyr[k] = hs[k + 2] - hs[k];
            mreg[k] = abs(gxr[k]) + abs(gyr[k]);
            M[ty * 4 + k + 1][tx + 1] = mreg[k];
        }
    }

    // ---- halo mag ring: 324 pixels ----
    if (tid < 324) {
        int ly, lx;
        if (tid < 130)      { ly = -1;        lx = tid - 1; }
        else if (tid < 260) { ly = 32;        lx = tid - 131; }
        else if (tid < 292) { ly = tid - 260; lx = -1; }
        else                { ly = tid - 292; lx = 128; }
        int py = tileY + ly, px = tileX + lx;
        int m = 0;
        if (py >= 0 && py < H && px >= 0 && px < W) {   // mag zero-padded outside
            int r0 = ly + 2, c0 = lx + 4;
            int gxv = (G[r0-1][c0+1] + 2*G[r0][c0+1] + G[r0+1][c0+1])
                    - (G[r0-1][c0-1] + 2*G[r0][c0-1] + G[r0+1][c0-1]);
            int gyv = (G[r0+1][c0-1] + 2*G[r0+1][c0] + G[r0+1][c0+1])
                    - (G[r0-1][c0-1] + 2*G[r0-1][c0] + G[r0-1][c0+1]);
            m = abs(gxv) + abs(gyv);
        }
        M[ly + 1][lx + 1] = m;
    }
    __syncthreads();

    // ---- NMS + thresholds from registers; q1/q2 from SMEM ----
#pragma unroll
    for (int k = 0; k < 4; k++) {
        int ly = ty * 4 + k;
        int py = tileY + ly, px = tileX + tx;
        int gxv = gxr[k], gyv = gyr[k], m = mreg[k];
        int mr = ly + 1, mc = tx + 1;

        unsigned ax = (unsigned)abs(gxv);
        unsigned ay = (unsigned)abs(gyv);
        unsigned long long ay30 = ((unsigned long long)ay) << 30;
        int q1, q2;
        if (ay30 < T1_30 * ax) {                   // b0: ~horizontal gradient
            q1 = M[mr][mc + 1]; q2 = M[mr][mc - 1];
        } else if (ay30 > T2_30 * ax) {            // b2: ~vertical
            q1 = M[mr + 1][mc]; q2 = M[mr - 1][mc];
        } else if ((gxv > 0) == (gyv > 0)) {       // b1
            q1 = M[mr + 1][mc + 1]; q2 = M[mr - 1][mc - 1];
        } else {                                   // b3
            q1 = M[mr - 1][mc + 1]; q2 = M[mr + 1][mc - 1];
        }
        bool keep   = (m >= q1) && (m >= q2);
        bool weak   = keep && (m > 40);
        bool strong = keep && (m > 85);

        unsigned wmask = __ballot_sync(0xffffffffu, weak);
        unsigned smask = __ballot_sync(0xffffffffu, strong);
        if ((tx & 31) == 0) {
            int wi = b * (H * WW) + py * WW + (px >> 5);
            g_weak[wi]   = wmask;
            g_strong[wi] = smask;
        }
    }
}

// ------------- Kernel 2: hysteresis, 64-bit column pairs (unchanged, ~11us) -------------
#define RPT64 3
#define NSLOT (128*RPT64)    // 384

__global__ void __launch_bounds__(1024, 1) k_hyst(float* __restrict__ out) {
    __shared__ union {
        struct {
            unsigned long long Bt[2][128][8];
            unsigned long long Bb[2][128][8];
        } x;
        unsigned SS[NSLOT * 16];
    } sm;

    int blk = blockIdx.x;
    int b = blk >> 2, s = blk & 3;
    int ybase = max(0, 128 * s - 100);
    int yend  = min(512, 128 * s + 228);
    int nrows = yend - ybase;
    int coreBase = 128 * s - ybase;

    int tid = threadIdx.x;
    int xp = tid & 7;
    int yg = tid >> 3;
    int slot0 = yg * RPT64;

    int wslot0 = (tid >> 5) * 12;
    int mind = max(0, max(coreBase - (wslot0 + 11), wslot0 - (coreBase + 127)));
    int tmax = 100 - mind;

    const unsigned long long* wb = (const unsigned long long*)(g_weak   + b * (H * WW));
    const unsigned long long* sb = (const unsigned long long*)(g_strong + b * (H * WW));

    unsigned long long wk[RPT64], st[RPT64];
#pragma unroll
    for (int i = 0; i < RPT64; i++) {
        int slot = slot0 + i;
        if (slot < nrows) {
            int gy = ybase + slot;
            wk[i] = wb[gy * 8 + xp];
            st[i] = sb[gy * 8 + xp];
        } else { wk[i] = 0ull; st[i] = 0ull; }
    }
    unsigned lmask = (xp == 0) ? 0u : 0xffffffffu;
    unsigned rmask = (xp == 7) ? 0u : 0xffffffffu;

    unsigned d = 1u;
    for (int t = 0; t < 100; ++t) {
        int tb = t & 1;
        bool act = (t <= tmax);
        unsigned long long h[RPT64];
        if (act) {
#pragma unroll
            for (int i = 0; i < RPT64; i++) {
                unsigned long long c = st[i];
                unsigned hi = (unsigned)(c >> 32), lo = (unsigned)c;
                unsigned lh = __shfl_up_sync(0xffffffffu, hi, 1) & lmask;
                unsigned rl = __shfl_down_sync(0xffffffffu, lo, 1) & rmask;
                h[i] = c | (c << 1) | (c >> 1)
                     | (unsigned long long)(lh >> 31)
                     | ((unsigned long long)(rl & 1u) << 63);
            }
            sm.x.Bt[tb][yg][xp] = h[0];
            sm.x.Bb[tb][yg][xp] = h[RPT64 - 1];
        }

        int conv = __syncthreads_or((int)d);
        if (!conv) break;

        if (act) {
            unsigned long long hup = (yg > 0)   ? sm.x.Bb[tb][yg - 1][xp] : 0ull;
            unsigned long long hdn = (yg < 127) ? sm.x.Bt[tb][yg + 1][xp] : 0ull;

            unsigned long long d64 = 0ull, ns;
            ns = wk[0] & (hup | h[0] | h[1]);  d64 |= ns ^ st[0]; st[0] = ns;
            ns = wk[1] & (h[0] | h[1] | h[2]); d64 |= ns ^ st[1]; st[1] = ns;
            ns = wk[2] & (h[1] | h[2] | hdn);  d64 |= ns ^ st[2]; st[2] = ns;
            d = (d64 != 0ull) ? 1u : 0u;
        } else {
            d = 0u;
        }
    }
    __syncthreads();

#pragma unroll
    for (int i = 0; i < RPT64; i++) {
        sm.SS[(slot0 + i) * 16 + 2 * xp]     = (unsigned)st[i];
        sm.SS[(slot0 + i) * 16 + 2 * xp + 1] = (unsigned)(st[i] >> 32);
    }
    __syncthreads();

    float* ob = out + (size_t)b * HW + (size_t)(128 * s) * W;
    for (int p4 = tid; p4 < 128 * 128; p4 += 1024) {
        int y = p4 >> 7;
        int x4 = p4 & 127;
        unsigned w = sm.SS[(coreBase + y) * 16 + (x4 >> 3)];
        int sh = (x4 & 7) * 4;
        float4 o;
        o.x = ((w >> (sh + 0)) & 1u) ? 255.0f : 0.0f;
        o.y = ((w >> (sh + 1)) & 1u) ? 255.0f : 0.0f;
        o.z = ((w >> (sh + 2)) & 1u) ? 255.0f : 0.0f;
        o.w = ((w >> (sh + 3)) & 1u) ? 255.0f : 0.0f;
        ((float4*)(ob + y * W))[x4] = o;
    }
}

extern "C" void kernel_launch(void* const* d_in, const int* in_sizes, int n_in,
                              void* d_out, int out_size) {
    const float* x = (const float*)d_in[0];
    float* out = (float*)d_out;

    k_gsobel<<<dim3(W/128, H/32, B), dim3(128, 8)>>>(x);
    k_hyst<<<B * 4, 1024>>>(out);
}

// round 11
// speedup vs baseline: 2.4402x; 1.0213x over previous
#include <cuda_runtime.h>
#include <cuda_bf16.h>
#include <stdint.h>

#define B 32
#define H 512
#define W 512
#define HW (H*W)            // 262144
#define WW 16               // words per row (512/32)

__device__ unsigned g_weak[B*H*WW];     // 1 MB
__device__ unsigned g_strong[B*H*WW];   // 1 MB

// ---- exact gray math ----
__device__ __forceinline__ float u8f(float v) {
    float t = __fmaf_rn(v, 128.0f, 128.0f);   // == rn(rn(v+1)*128), see R9 proof
    t = fminf(fmaxf(t, 0.0f), 255.0f);
    return floorf(t);
}

__device__ __forceinline__ int grayf(float r, float g, float b) {
    float t = __fadd_rn(__fadd_rn(__fmul_rn(0.299f, u8f(r)),
                                  __fmul_rn(0.587f, u8f(g))),
                        __fmul_rn(0.114f, u8f(b)));
    return (int)rintf(t);   // round half to even, matches jnp.round
}

// angle-bin constants at 2^30 scale (decision-exact, see R9)
#define T1_30 444758425ULL
#define T2_30 2592242073ULL

// ------------- Fused Kernel 1: RGB -> gray -> Sobel -> NMS -> bitmasks -------------
// Tile 128x16 core, block (128,4) = 512 threads, __launch_bounds__(512,2):
// TWO independent blocks per SM so fill-phase DRAM latency of one block is
// covered by the compute phase of the other (was 1 block/SM at 1024 threads).
__global__ void __launch_bounds__(512, 2) k_gsobel(const float* __restrict__ x) {
    __shared__ int G[20][136];   // gray, rows tileY-2..+17, cols tileX-4..+131 (10.6KB)
    __shared__ int M[18][132];   // mag,  rows tileY-1..+16, cols tileX-1..+130 ( 9.3KB)

    int b = blockIdx.z;
    int tileX = blockIdx.x * 128, tileY = blockIdx.y * 16;
    int tx = threadIdx.x, ty = threadIdx.y;
    int tid = ty * 128 + tx;
    const float* xr = x + (size_t)b * 3 * HW;

    // ---- gray fill: 20 rows x 34 aligned 4-pixel groups (680 groups / 512 thr) ----
    for (int i = tid; i < 20 * 34; i += 512) {
        int r = i / 34, j = i - r * 34;
        int gy = min(max(tileY - 2 + r, 0), H - 1);
        int gx0 = tileX - 4 + 4 * j;
        int4 o;
        if (gx0 >= 0 && gx0 <= W - 4) {          // aligned fast path
            const float4* pr = (const float4*)(xr + (size_t)gy * W) + (gx0 >> 2);
            float4 rr = pr[0];
            float4 gg = pr[HW / 4];
            float4 bb = pr[2 * (HW / 4)];
            o.x = grayf(rr.x, gg.x, bb.x);
            o.y = grayf(rr.y, gg.y, bb.y);
            o.z = grayf(rr.z, gg.z, bb.z);
            o.w = grayf(rr.w, gg.w, bb.w);
        } else {                                  // border clamp (x-edge tiles only)
            int v[4];
#pragma unroll
            for (int e = 0; e < 4; e++) {
                int gx = min(max(gx0 + e, 0), W - 1);
                int p = gy * W + gx;
                v[e] = grayf(xr[p], xr[HW + p], xr[2 * HW + p]);
            }
            o.x = v[0]; o.y = v[1]; o.z = v[2]; o.w = v[3];
        }
        *(int4*)&G[r][4 * j] = o;
    }
    __syncthreads();

    // ---- Sobel for own 4 core pixels (rows ty*4..ty*4+3), separable ----
    int gxr[4], gyr[4], mreg[4];
    {
        int cl = tx + 3, cc = tx + 4, cr = tx + 5;   // G cols: px-1, px, px+1
        int rb = ty * 4 + 1;                         // G row of (core row ly) - 1
        int L[6], C[6], R[6], hs[6];
#pragma unroll
        for (int q = 0; q < 6; q++) {
            L[q] = G[rb + q][cl];
            C[q] = G[rb + q][cc];
            R[q] = G[rb + q][cr];
            hs[q] = (L[q] + R[q]) + 2 * C[q];        // shared: hs2_k == hs0_{k+2}
        }
#pragma unroll
        for (int k = 0; k < 4; k++) {
            int vr = R[k] + 2 * R[k + 1] + R[k + 2];
            int vl = L[k] + 2 * L[k + 1] + L[k + 2];
            gxr[k] = vr - vl;
            gyr[k] = hs[k + 2] - hs[k];
            mreg[k] = abs(gxr[k]) + abs(gyr[k]);
            M[ty * 4 + k + 1][tx + 1] = mreg[k];
        }
    }

    // ---- halo mag ring: 292 pixels (rows -1,16 width 130; cols -1,128 rows 0..15) ----
    if (tid < 292) {
        int ly, lx;
        if (tid < 130)      { ly = -1;        lx = tid - 1; }
        else if (tid < 260) { ly = 16;        lx = tid - 131; }
        else if (tid < 276) { ly = tid - 260; lx = -1; }
        else                { ly = tid - 276; lx = 128; }
        int py = tileY + ly, px = tileX + lx;
        int m = 0;
        if (py >= 0 && py < H && px >= 0 && px < W) {   // mag zero-padded outside
            int r0 = ly + 2, c0 = lx + 4;
            int gxv = (G[r0-1][c0+1] + 2*G[r0][c0+1] + G[r0+1][c0+1])
                    - (G[r0-1][c0-1] + 2*G[r0][c0-1] + G[r0+1][c0-1]);
            int gyv = (G[r0+1][c0-1] + 2*G[r0+1][c0] + G[r0+1][c0+1])
                    - (G[r0-1][c0-1] + 2*G[r0-1][c0] + G[r0-1][c0+1]);
            m = abs(gxv) + abs(gyv);
        }
        M[ly + 1][lx + 1] = m;
    }
    __syncthreads();

    // ---- NMS + thresholds from registers; q1/q2 from SMEM ----
#pragma unroll
    for (int k = 0; k < 4; k++) {
        int ly = ty * 4 + k;
        int py = tileY + ly, px = tileX + tx;
        int gxv = gxr[k], gyv = gyr[k], m = mreg[k];
        int mr = ly + 1, mc = tx + 1;

        unsigned ax = (unsigned)abs(gxv);
        unsigned ay = (unsigned)abs(gyv);
        unsigned long long ay30 = ((unsigned long long)ay) << 30;
        int q1, q2;
        if (ay30 < T1_30 * ax) {                   // b0: ~horizontal gradient
            q1 = M[mr][mc + 1]; q2 = M[mr][mc - 1];
        } else if (ay30 > T2_30 * ax) {            // b2: ~vertical
            q1 = M[mr + 1][mc]; q2 = M[mr - 1][mc];
        } else if ((gxv > 0) == (gyv > 0)) {       // b1
            q1 = M[mr + 1][mc + 1]; q2 = M[mr - 1][mc - 1];
        } else {                                   // b3
            q1 = M[mr - 1][mc + 1]; q2 = M[mr + 1][mc - 1];
        }
        bool keep   = (m >= q1) && (m >= q2);
        bool weak   = keep && (m > 40);
        bool strong = keep && (m > 85);

        unsigned wmask = __ballot_sync(0xffffffffu, weak);
        unsigned smask = __ballot_sync(0xffffffffu, strong);
        if ((tx & 31) == 0) {
            int wi = b * (H * WW) + py * WW + (px >> 5);
            g_weak[wi]   = wmask;
            g_strong[wi] = smask;
        }
    }
}

// ------------- Kernel 2: hysteresis, 64-bit column pairs (unchanged, ~10.5us) -------------
#define RPT64 3
#define NSLOT (128*RPT64)    // 384

__global__ void __launch_bounds__(1024, 1) k_hyst(float* __restrict__ out) {
    __shared__ union {
        struct {
            unsigned long long Bt[2][128][8];
            unsigned long long Bb[2][128][8];
        } x;
        unsigned SS[NSLOT * 16];
    } sm;

    int blk = blockIdx.x;
    int b = blk >> 2, s = blk & 3;
    int ybase = max(0, 128 * s - 100);
    int yend  = min(512, 128 * s + 228);
    int nrows = yend - ybase;
    int coreBase = 128 * s - ybase;

    int tid = threadIdx.x;
    int xp = tid & 7;
    int yg = tid >> 3;
    int slot0 = yg * RPT64;

    int wslot0 = (tid >> 5) * 12;
    int mind = max(0, max(coreBase - (wslot0 + 11), wslot0 - (coreBase + 127)));
    int tmax = 100 - mind;

    const unsigned long long* wb = (const unsigned long long*)(g_weak   + b * (H * WW));
    const unsigned long long* sb = (const unsigned long long*)(g_strong + b * (H * WW));

    unsigned long long wk[RPT64], st[RPT64];
#pragma unroll
    for (int i = 0; i < RPT64; i++) {
        int slot = slot0 + i;
        if (slot < nrows) {
            int gy = ybase + slot;
            wk[i] = wb[gy * 8 + xp];
            st[i] = sb[gy * 8 + xp];
        } else { wk[i] = 0ull; st[i] = 0ull; }
    }
    unsigned lmask = (xp == 0) ? 0u : 0xffffffffu;
    unsigned rmask = (xp == 7) ? 0u : 0xffffffffu;

    unsigned d = 1u;
    for (int t = 0; t < 100; ++t) {
        int tb = t & 1;
        bool act = (t <= tmax);
        unsigned long long h[RPT64];
        if (act) {
#pragma unroll
            for (int i = 0; i < RPT64; i++) {
                unsigned long long c = st[i];
                unsigned hi = (unsigned)(c >> 32), lo = (unsigned)c;
                unsigned lh = __shfl_up_sync(0xffffffffu, hi, 1) & lmask;
                unsigned rl = __shfl_down_sync(0xffffffffu, lo, 1) & rmask;
                h[i] = c | (c << 1) | (c >> 1)
                     | (unsigned long long)(lh >> 31)
                     | ((unsigned long long)(rl & 1u) << 63);
            }
            sm.x.Bt[tb][yg][xp] = h[0];
            sm.x.Bb[tb][yg][xp] = h[RPT64 - 1];
        }

        int conv = __syncthreads_or((int)d);
        if (!conv) break;

        if (act) {
            unsigned long long hup = (yg > 0)   ? sm.x.Bb[tb][yg - 1][xp] : 0ull;
            unsigned long long hdn = (yg < 127) ? sm.x.Bt[tb][yg + 1][xp] : 0ull;

            unsigned long long d64 = 0ull, ns;
            ns = wk[0] & (hup | h[0] | h[1]);  d64 |= ns ^ st[0]; st[0] = ns;
            ns = wk[1] & (h[0] | h[1] | h[2]); d64 |= ns ^ st[1]; st[1] = ns;
            ns = wk[2] & (h[1] | h[2] | hdn);  d64 |= ns ^ st[2]; st[2] = ns;
            d = (d64 != 0ull) ? 1u : 0u;
        } else {
            d = 0u;
        }
    }
    __syncthreads();

#pragma unroll
    for (int i = 0; i < RPT64; i++) {
        sm.SS[(slot0 + i) * 16 + 2 * xp]     = (unsigned)st[i];
        sm.SS[(slot0 + i) * 16 + 2 * xp + 1] = (unsigned)(st[i] >> 32);
    }
    __syncthreads();

    float* ob = out + (size_t)b * HW + (size_t)(128 * s) * W;
    for (int p4 = tid; p4 < 128 * 128; p4 += 1024) {
        int y = p4 >> 7;
        int x4 = p4 & 127;
        unsigned w = sm.SS[(coreBase + y) * 16 + (x4 >> 3)];
        int sh = (x4 & 7) * 4;
        float4 o;
        o.x = ((w >> (sh + 0)) & 1u) ? 255.0f : 0.0f;
        o.y = ((w >> (sh + 1)) & 1u) ? 255.0f : 0.0f;
        o.z = ((w >> (sh + 2)) & 1u) ? 255.0f : 0.0f;
        o.w = ((w >> (sh + 3)) & 1u) ? 255.0f : 0.0f;
        ((float4*)(ob + y * W))[x4] = o;
    }
}

extern "C" void kernel_launch(void* const* d_in, const int* in_sizes, int n_in,
                              void* d_out, int out_size) {
    const float* x = (const float*)d_in[0];
    float* out = (float*)d_out;

    k_gsobel<<<dim3(W/128, H/16, B), dim3(128, 4)>>>(x);
    k_hyst<<<B * 4, 1024>>>(out);
}

// round 14
// speedup vs baseline: 2.4949x; 1.0224x over previous
#include <cuda_runtime.h>
#include <cuda_bf16.h>
#include <stdint.h>

#define B 32
#define H 512
#define W 512
#define HW (H*W)            // 262144
#define WW 16               // words per row (512/32)

__device__ unsigned g_weak[B*H*WW];     // 1 MB
__device__ unsigned g_strong[B*H*WW];   // 1 MB

// ---- exact gray math ----
// t = rn(128v+128) >= 0 always (input is tanh >= -1; v=-1 gives exactly 0),
// so the lower clamp is dropped. floor(min(t,255)) == floor(clip(t,0,255)).
__device__ __forceinline__ float u8f(float v) {
    float t = __fmaf_rn(v, 128.0f, 128.0f);   // == rn(rn(v+1)*128), see R9 proof
    return floorf(fminf(t, 255.0f));
}

__device__ __forceinline__ int grayf(float r, float g, float b) {
    float t = __fadd_rn(__fadd_rn(__fmul_rn(0.299f, u8f(r)),
                                  __fmul_rn(0.587f, u8f(g))),
                        __fmul_rn(0.114f, u8f(b)));
    return __float2int_rn(t);   // single F2I, round half to even == jnp.round
}

// angle-bin constants at 2^30 scale (decision-exact, see R9)
#define T1_30 444758425ULL
#define T2_30 2592242073ULL

// ------------- Fused Kernel 1: RGB -> gray -> Sobel -> NMS -> bitmasks -------------
__global__ void __launch_bounds__(512, 2) k_gsobel(const float* __restrict__ x) {
    __shared__ int G[20][136];   // gray, rows tileY-2..+17, cols tileX-4..+131
    __shared__ int M[18][132];   // mag,  rows tileY-1..+16, cols tileX-1..+130

    int b = blockIdx.z;
    int tileX = blockIdx.x * 128, tileY = blockIdx.y * 16;
    int tx = threadIdx.x, ty = threadIdx.y;
    int tid = ty * 128 + tx;
    const float* xr = x + (size_t)b * 3 * HW;

    // ---- gray fill: 20 rows x 34 aligned 4-pixel groups ----
    for (int i = tid; i < 20 * 34; i += 512) {
        int r = i / 34, j = i - r * 34;
        int gy = min(max(tileY - 2 + r, 0), H - 1);
        int gx0 = tileX - 4 + 4 * j;
        int4 o;
        if (gx0 >= 0 && gx0 <= W - 4) {          // aligned fast path
            const float4* pr = (const float4*)(xr + (size_t)gy * W) + (gx0 >> 2);
            float4 rr = pr[0];
            float4 gg = pr[HW / 4];
            float4 bb = pr[2 * (HW / 4)];
            o.x = grayf(rr.x, gg.x, bb.x);
            o.y = grayf(rr.y, gg.y, bb.y);
            o.z = grayf(rr.z, gg.z, bb.z);
            o.w = grayf(rr.w, gg.w, bb.w);
        } else {                                  // border clamp (x-edge tiles only)
            int v[4];
#pragma unroll
            for (int e = 0; e < 4; e++) {
                int gx = min(max(gx0 + e, 0), W - 1);
                int p = gy * W + gx;
                v[e] = grayf(xr[p], xr[HW + p], xr[2 * HW + p]);
            }
            o.x = v[0]; o.y = v[1]; o.z = v[2]; o.w = v[3];
        }
        *(int4*)&G[r][4 * j] = o;
    }
    __syncthreads();

    // ---- Sobel for own 4 core pixels (rows ty*4..ty*4+3), separable ----
    int gxr[4], gyr[4], mreg[4];
    {
        int cl = tx + 3, cc = tx + 4, cr = tx + 5;   // G cols: px-1, px, px+1
        int rb = ty * 4 + 1;                         // G row of (core row ly) - 1
        int L[6], C[6], R[6], hs[6];
#pragma unroll
        for (int q = 0; q < 6; q++) {
            L[q] = G[rb + q][cl];
            C[q] = G[rb + q][cc];
            R[q] = G[rb + q][cr];
            hs[q] = (L[q] + R[q]) + 2 * C[q];        // shared: hs2_k == hs0_{k+2}
        }
#pragma unroll
        for (int k = 0; k < 4; k++) {
            int vr = R[k] + 2 * R[k + 1] + R[k + 2];
            int vl = L[k] + 2 * L[k + 1] + L[k + 2];
            gxr[k] = vr - vl;
            gyr[k] = hs[k + 2] - hs[k];
            mreg[k] = abs(gxr[k]) + abs(gyr[k]);
            M[ty * 4 + k + 1][tx + 1] = mreg[k];
        }
    }

    // ---- halo mag ring: 292 pixels ----
    if (tid < 292) {
        int ly, lx;
        if (tid < 130)      { ly = -1;        lx = tid - 1; }
        else if (tid < 260) { ly = 16;        lx = tid - 131; }
        else if (tid < 276) { ly = tid - 260; lx = -1; }
        else                { ly = tid - 276; lx = 128; }
        int py = tileY + ly, px = tileX + lx;
        int m = 0;
        if (py >= 0 && py < H && px >= 0 && px < W) {   // mag zero-padded outside
            int r0 = ly + 2, c0 = lx + 4;
            int gxv = (G[r0-1][c0+1] + 2*G[r0][c0+1] + G[r0+1][c0+1])
                    - (G[r0-1][c0-1] + 2*G[r0][c0-1] + G[r0+1][c0-1]);
            int gyv = (G[r0+1][c0-1] + 2*G[r0+1][c0] + G[r0+1][c0+1])
                    - (G[r0-1][c0-1] + 2*G[r0-1][c0] + G[r0-1][c0+1]);
            m = abs(gxv) + abs(gyv);
        }
        M[ly + 1][lx + 1] = m;
    }
    __syncthreads();

    // ---- NMS + thresholds: BRANCHLESS bin select via flat offset ----
    // b0 -> off=+1, b2 -> +132, b1 -> +133, b3 -> -131; q1 = Mf[base+off], q2 = Mf[base-off].
    const int* Mf = &M[0][0];
#pragma unroll
    for (int k = 0; k < 4; k++) {
        int ly = ty * 4 + k;
        int py = tileY + ly, px = tileX + tx;
        int gxv = gxr[k], gyv = gyr[k], m = mreg[k];
        int base = (ly + 1) * 132 + (tx + 1);

        unsigned ax = (unsigned)abs(gxv);
        unsigned ay = (unsigned)abs(gyv);
        unsigned long long ay30 = ((unsigned long long)ay) << 30;
        bool p0 = ay30 < T1_30 * ax;               // ~horizontal gradient
        bool p2 = ay30 > T2_30 * ax;               // ~vertical
        bool pd = ((gxv ^ gyv) >= 0);              // same sign (only matters when !p0 && !p2)
        int off = p0 ? 1 : (p2 ? 132 : (pd ? 133 : -131));
        int q1 = Mf[base + off];
        int q2 = Mf[base - off];

        bool keep   = (m >= q1) && (m >= q2);
        bool weak   = keep && (m > 40);
        bool strong = keep && (m > 85);

        unsigned wmask = __ballot_sync(0xffffffffu, weak);
        unsigned smask = __ballot_sync(0xffffffffu, strong);
        if ((tx & 31) == 0) {
            int wi = b * (H * WW) + py * WW + (px >> 5);
            g_weak[wi]   = wmask;
            g_strong[wi] = smask;
        }
    }
}

// ------------- Kernel 2: hysteresis, 64-bit column pairs (unchanged, ~10.8us) -------------
#define RPT64 3
#define NSLOT (128*RPT64)    // 384

__global__ void __launch_bounds__(1024, 1) k_hyst(float* __restrict__ out) {
    __shared__ union {
        struct {
            unsigned long long Bt[2][128][8];
            unsigned long long Bb[2][128][8];
        } x;
        unsigned SS[NSLOT * 16];
    } sm;

    int blk = blockIdx.x;
    int b = blk >> 2, s = blk & 3;
    int ybase = max(0, 128 * s - 100);
    int yend  = min(512, 128 * s + 228);
    int nrows = yend - ybase;
    int coreBase = 128 * s - ybase;

    int tid = threadIdx.x;
    int xp = tid & 7;
    int yg = tid >> 3;
    int slot0 = yg * RPT64;

    int wslot0 = (tid >> 5) * 12;
    int mind = max(0, max(coreBase - (wslot0 + 11), wslot0 - (coreBase + 127)));
    int tmax = 100 - mind;

    const unsigned long long* wb = (const unsigned long long*)(g_weak   + b * (H * WW));
    const unsigned long long* sb = (const unsigned long long*)(g_strong + b * (H * WW));

    unsigned long long wk[RPT64], st[RPT64];
#pragma unroll
    for (int i = 0; i < RPT64; i++) {
        int slot = slot0 + i;
        if (slot < nrows) {
            int gy = ybase + slot;
            wk[i] = wb[gy * 8 + xp];
            st[i] = sb[gy * 8 + xp];
        } else { wk[i] = 0ull; st[i] = 0ull; }
    }
    unsigned lmask = (xp == 0) ? 0u : 0xffffffffu;
    unsigned rmask = (xp == 7) ? 0u : 0xffffffffu;

    unsigned d = 1u;
    for (int t = 0; t < 100; ++t) {
        int tb = t & 1;
        bool act = (t <= tmax);
        unsigned long long h[RPT64];
        if (act) {
#pragma unroll
            for (int i = 0; i < RPT64; i++) {
                unsigned long long c = st[i];
                unsigned hi = (unsigned)(c >> 32), lo = (unsigned)c;
                unsigned lh = __shfl_up_sync(0xffffffffu, hi, 1) & lmask;
                unsigned rl = __shfl_down_sync(0xffffffffu, lo, 1) & rmask;
                h[i] = c | (c << 1) | (c >> 1)
                     | (unsigned long long)(lh >> 31)
                     | ((unsigned long long)(rl & 1u) << 63);
            }
            sm.x.Bt[tb][yg][xp] = h[0];
            sm.x.Bb[tb][yg][xp] = h[RPT64 - 1];
        }

        int conv = __syncthreads_or((int)d);
        if (!conv) break;

        if (act) {
            unsigned long long hup = (yg > 0)   ? sm.x.Bb[tb][yg - 1][xp] : 0ull;
            unsigned long long hdn = (yg < 127) ? sm.x.Bt[tb][yg + 1][xp] : 0ull;

            unsigned long long d64 = 0ull, ns;
            ns = wk[0] & (hup | h[0] | h[1]);  d64 |= ns ^ st[0]; st[0] = ns;
            ns = wk[1] & (h[0] | h[1] | h[2]); d64 |= ns ^ st[1]; st[1] = ns;
            ns = wk[2] & (h[1] | h[2] | hdn);  d64 |= ns ^ st[2]; st[2] = ns;
            d = (d64 != 0ull) ? 1u : 0u;
        } else {
            d = 0u;
        }
    }
    __syncthreads();

#pragma unroll
    for (int i = 0; i < RPT64; i++) {
        sm.SS[(slot0 + i) * 16 + 2 * xp]     = (unsigned)st[i];
        sm.SS[(slot0 + i) * 16 + 2 * xp + 1] = (unsigned)(st[i] >> 32);
    }
    __syncthreads();

    float* ob = out + (size_t)b * HW + (size_t)(128 * s) * W;
    for (int p4 = tid; p4 < 128 * 128; p4 += 1024) {
        int y = p4 >> 7;
        int x4 = p4 & 127;
        unsigned w = sm.SS[(coreBase + y) * 16 + (x4 >> 3)];
        int sh = (x4 & 7) * 4;
        float4 o;
        o.x = ((w >> (sh + 0)) & 1u) ? 255.0f : 0.0f;
        o.y = ((w >> (sh + 1)) & 1u) ? 255.0f : 0.0f;
        o.z = ((w >> (sh + 2)) & 1u) ? 255.0f : 0.0f;
        o.w = ((w >> (sh + 3)) & 1u) ? 255.0f : 0.0f;
        ((float4*)(ob + y * W))[x4] = o;
    }
}

extern "C" void kernel_launch(void* const* d_in, const int* in_sizes, int n_in,
                              void* d_out, int out_size) {
    const float* x = (const float*)d_in[0];
    float* out = (float*)d_out;

    k_gsobel<<<dim3(W/128, H/16, B), dim3(128, 4)>>>(x);
    k_hyst<<<B * 4, 1024>>>(out);
}